// round 14
// baseline (speedup 1.0000x reference)
#include <cuda_runtime.h>
#include <cstdint>

#define E_NUM   500000
#define H_DIM   256
#define PAIRS   (E_NUM / 2)      // 250000
#define BN_EPS  1e-5f
#define GRID    296              // 148 SMs x 2 co-resident blocks (3/SM toxic: R4/R10)
#define PER1    848              // pairs/block for stats, blocks 1..295
#define NTILES  31250            // E/16 edge tiles for tensor phase 2
#define NWARPS  (GRID * 8)       // 2368 warps
#define NFAKE   103648           // zero-padded fake edges in stats (exact for PER1=848)

typedef unsigned long long u64;

// nc storage is PAIR-PERMUTED per row: [c0,c4,c1,c5,c2,c6,c3,c7]
// => original col j (j<4) at pos 2j ; col j+4 at pos 2j+1 ; K-slot pair (q4,q4+4)
//    is one aligned float2 at float2-index q4. Pure address permutation.

// -------- device scratch (static, no allocation) --------
__device__ float g_sum[H_DIM];                     // zero-init
__device__ float g_sumsq[H_DIM];
__device__ __align__(16) float g_ncf[(size_t)E_NUM * 8];  // permuted raw (src+tgt) [E,8]
__device__ float g_Craw[H_DIM * 8];                // W2@Wv@Wo@Wp
__device__ float g_biaspart[8];                    // b2@P2 + bv@P1 + bo@Wp + bp
__device__ unsigned g_arrive = 0;
__device__ volatile unsigned g_release = 0;
__device__ unsigned g_finish = 0;

// -------- helpers --------
__device__ __forceinline__ float wred(float v) {
    v += __shfl_down_sync(0xffffffffu, v, 16);
    v += __shfl_down_sync(0xffffffffu, v, 8);
    v += __shfl_down_sync(0xffffffffu, v, 4);
    v += __shfl_down_sync(0xffffffffu, v, 2);
    v += __shfl_down_sync(0xffffffffu, v, 1);
    return v;
}
__device__ __forceinline__ unsigned tf32r(float x) {
    unsigned u;
    asm("cvt.rna.tf32.f32 %0, %1;" : "=r"(u) : "f"(x));
    return u;
}
__device__ __forceinline__ u64 pack2(float lo, float hi) {
    u64 r;
    asm("mov.b64 %0, {%1, %2};" : "=l"(r)
        : "r"(__float_as_uint(lo)), "r"(__float_as_uint(hi)));
    return r;
}
__device__ __forceinline__ void unpack2(u64 v, float &lo, float &hi) {
    unsigned int a, b;
    asm("mov.b64 {%0, %1}, %2;" : "=r"(a), "=r"(b) : "l"(v));
    lo = __uint_as_float(a); hi = __uint_as_float(b);
}
__device__ __forceinline__ u64 fma2(u64 a, u64 b, u64 c) {
    u64 d;
    asm("fma.rn.f32x2 %0, %1, %2, %3;" : "=l"(d) : "l"(a), "l"(b), "l"(c));
    return d;
}
__device__ __forceinline__ u64 add2(u64 a, u64 b) {
    u64 d;
    asm("add.rn.f32x2 %0, %1, %2;" : "=l"(d) : "l"(a), "l"(b));
    return d;
}
__device__ __forceinline__ void mma_init(float &d0, float &d1, float &d2, float &d3,
    unsigned a0, unsigned a1, unsigned a2, unsigned a3,
    unsigned b0, unsigned b1,
    float c0, float c1, float c2, float c3) {
    asm("mma.sync.aligned.m16n8k8.row.col.f32.tf32.tf32.f32 "
        "{%0,%1,%2,%3}, {%4,%5,%6,%7}, {%8,%9}, {%10,%11,%12,%13};"
        : "=f"(d0), "=f"(d1), "=f"(d2), "=f"(d3)
        : "r"(a0), "r"(a1), "r"(a2), "r"(a3), "r"(b0), "r"(b1),
          "f"(c0), "f"(c1), "f"(c2), "f"(c3));
}
__device__ __forceinline__ void mma_acc(float &c0, float &c1, float &c2, float &c3,
    unsigned a0, unsigned a1, unsigned a2, unsigned a3,
    unsigned b0, unsigned b1) {
    asm("mma.sync.aligned.m16n8k8.row.col.f32.tf32.tf32.f32 "
        "{%0,%1,%2,%3}, {%4,%5,%6,%7}, {%8,%9}, {%0,%1,%2,%3};"
        : "+f"(c0), "+f"(c1), "+f"(c2), "+f"(c3)
        : "r"(a0), "r"(a1), "r"(a2), "r"(a3), "r"(b0), "r"(b1));
}

// gather one 256-pair tile: raw (src+tgt), pair-permuted storage
__device__ __forceinline__ void gather_tile(
    int base, int e1, float* buf, int t,
    const int* __restrict__ eidx, const float4* __restrict__ nf4)
{
    float4* row0 = (float4*)(buf + (2 * t) * 8);
    int p = base + t;
    if (p < e1) {
        int e0 = 2 * p;
        int sA = eidx[e0],         sB = eidx[e0 + 1];
        int dA = eidx[E_NUM + e0], dB = eidx[E_NUM + e0 + 1];
        float4 sa0 = nf4[2*sA], sa1 = nf4[2*sA+1];
        float4 da0 = nf4[2*dA], da1 = nf4[2*dA+1];
        float4 sb0 = nf4[2*sB], sb1 = nf4[2*sB+1];
        float4 db0 = nf4[2*dB], db1 = nf4[2*dB+1];
        // edge 2p cols: l0..l7 ; permuted rows [c0,c4,c1,c5] [c2,c6,c3,c7]
        float l0 = sa0.x+da0.x, l1 = sa0.y+da0.y, l2 = sa0.z+da0.z, l3 = sa0.w+da0.w;
        float l4 = sa1.x+da1.x, l5 = sa1.y+da1.y, l6 = sa1.z+da1.z, l7 = sa1.w+da1.w;
        float h0 = sb0.x+db0.x, h1 = sb0.y+db0.y, h2 = sb0.z+db0.z, h3 = sb0.w+db0.w;
        float h4 = sb1.x+db1.x, h5 = sb1.y+db1.y, h6 = sb1.z+db1.z, h7 = sb1.w+db1.w;
        float4 vl0 = make_float4(l0, l4, l1, l5);
        float4 vl1 = make_float4(l2, l6, l3, l7);
        float4 vh0 = make_float4(h0, h4, h1, h5);
        float4 vh1 = make_float4(h2, h6, h3, h7);
        row0[0] = vl0; row0[1] = vl1; row0[2] = vh0; row0[3] = vh1;
        float4* nr = (float4*)(g_ncf + (size_t)(2 * p) * 8);
        nr[0] = vl0; nr[1] = vl1; nr[2] = vh0; nr[3] = vh1;
    } else {
        float4 z = make_float4(0.f, 0.f, 0.f, 0.f);
        row0[0] = z; row0[1] = z; row0[2] = z; row0[3] = z;
    }
}

__global__ void __launch_bounds__(256, 2)
fused(const float* __restrict__ ea, const float* __restrict__ nf,
      const int*   __restrict__ eidx,
      const float* __restrict__ W1, const float* __restrict__ b1,
      const float* __restrict__ gamma, const float* __restrict__ beta,
      const float* __restrict__ W2, const float* __restrict__ b2,
      const float* __restrict__ Wv, const float* __restrict__ bv,
      const float* __restrict__ Wo, const float* __restrict__ bo,
      const float* __restrict__ Wp, const float* __restrict__ bp,
      float* __restrict__ out)
{
    // s_buf: phase1 buf0 (16KB of it) / block0 chain (2x2304 floats = 18KB)
    __shared__ __align__(16) unsigned char s_buf[18432];
    __shared__ __align__(16) float tile2[4096];     // phase1 buf1 (16KB)
    __shared__ __align__(16) float2 w1frag[1024];   // GEMM1 B frags = tf32(0.5*W1)
    __shared__ __align__(16) float2 mfrag[1024];    // GEMM2 B frags (tau-permuted)
    __shared__ float2 b1frag[128];                  // b1 col pairs
    __shared__ float dhf[8];
    __shared__ float a_s[H_DIM], c_s[H_DIM];

    const int t = threadIdx.x;
    const int b = blockIdx.x;
    const int lane = t & 31, warp = t >> 5;
    const int g = lane >> 2, q4 = lane & 3;

    // ---- W1 (0.5-folded) / b1 fragment tables ----
    for (int i = t; i < 1024; i += 256) {
        int q = i >> 5, l = i & 31;
        int kk = l & 3, nn = l >> 2;
        float w0 = 0.5f * W1[kk * H_DIM + q * 8 + nn];
        float w1v = 0.5f * W1[(kk + 4) * H_DIM + q * 8 + nn];
        w1frag[i] = make_float2(__uint_as_float(tf32r(w0)), __uint_as_float(tf32r(w1v)));
    }
    for (int i = t; i < 128; i += 256) {
        int q = i >> 2, qq = i & 3;
        b1frag[i] = make_float2(b1[q * 8 + 2 * qq], b1[q * 8 + 2 * qq + 1]);
    }
    __syncthreads();

    if (b == 0) {
        // ============ weight chain (overlaps the stats pass) ============
        float* bufA = (float*)s_buf;
        float* bufB = bufA + 2304;
        for (int i = t; i < H_DIM * 8; i += 256)
            bufA[(i >> 3) * 9 + (i & 7)] = Wp[i];
        __syncthreads();
        float biask = 0.f;
        for (int j = lane; j < H_DIM; j += 32) biask += bo[j] * bufA[j * 9 + warp];
        for (int jj = warp; jj < H_DIM; jj += 8) {
            float a0=0,a1=0,a2=0,a3=0,a4=0,a5=0,a6=0,a7=0;
            #pragma unroll
            for (int qb = 0; qb < 8; qb++) {
                int q = qb * 32 + lane;
                float av = Wo[jj * H_DIM + q];
                const float* ir = bufA + q * 9;
                a0 += av*ir[0]; a1 += av*ir[1]; a2 += av*ir[2]; a3 += av*ir[3];
                a4 += av*ir[4]; a5 += av*ir[5]; a6 += av*ir[6]; a7 += av*ir[7];
            }
            a0=wred(a0); a1=wred(a1); a2=wred(a2); a3=wred(a3);
            a4=wred(a4); a5=wred(a5); a6=wred(a6); a7=wred(a7);
            if (lane == 0) {
                float* orow = bufB + jj * 9;
                orow[0]=a0; orow[1]=a1; orow[2]=a2; orow[3]=a3;
                orow[4]=a4; orow[5]=a5; orow[6]=a6; orow[7]=a7;
            }
        }
        __syncthreads();
        for (int j = lane; j < H_DIM; j += 32) biask += bv[j] * bufB[j * 9 + warp];
        for (int jj = warp; jj < H_DIM; jj += 8) {
            float a0=0,a1=0,a2=0,a3=0,a4=0,a5=0,a6=0,a7=0;
            #pragma unroll
            for (int qb = 0; qb < 8; qb++) {
                int q = qb * 32 + lane;
                float av = Wv[jj * H_DIM + q];
                const float* ir = bufB + q * 9;
                a0 += av*ir[0]; a1 += av*ir[1]; a2 += av*ir[2]; a3 += av*ir[3];
                a4 += av*ir[4]; a5 += av*ir[5]; a6 += av*ir[6]; a7 += av*ir[7];
            }
            a0=wred(a0); a1=wred(a1); a2=wred(a2); a3=wred(a3);
            a4=wred(a4); a5=wred(a5); a6=wred(a6); a7=wred(a7);
            if (lane == 0) {
                float* orow = bufA + jj * 9;
                orow[0]=a0; orow[1]=a1; orow[2]=a2; orow[3]=a3;
                orow[4]=a4; orow[5]=a5; orow[6]=a6; orow[7]=a7;
            }
        }
        __syncthreads();
        for (int j = lane; j < H_DIM; j += 32) biask += b2[j] * bufA[j * 9 + warp];
        for (int jj = warp; jj < H_DIM; jj += 8) {
            float a0=0,a1=0,a2=0,a3=0,a4=0,a5=0,a6=0,a7=0;
            #pragma unroll
            for (int qb = 0; qb < 8; qb++) {
                int q = qb * 32 + lane;
                float av = W2[jj * H_DIM + q];
                const float* ir = bufA + q * 9;
                a0 += av*ir[0]; a1 += av*ir[1]; a2 += av*ir[2]; a3 += av*ir[3];
                a4 += av*ir[4]; a5 += av*ir[5]; a6 += av*ir[6]; a7 += av*ir[7];
            }
            a0=wred(a0); a1=wred(a1); a2=wred(a2); a3=wred(a3);
            a4=wred(a4); a5=wred(a5); a6=wred(a6); a7=wred(a7);
            if (lane == 0) {
                float* orow = g_Craw + jj * 8;
                orow[0]=a0; orow[1]=a1; orow[2]=a2; orow[3]=a3;
                orow[4]=a4; orow[5]=a5; orow[6]=a6; orow[7]=a7;
            }
        }
        biask = wred(biask);
        if (lane == 0) g_biaspart[warp] = biask + bp[warp];
    } else {
        // ===== phase 1: double-buffered gather + tensor relu stats =====
        int s1 = (b - 1) * PER1;
        int e1 = s1 + PER1; if (e1 > PAIRS) e1 = PAIRS;
        const float4* nf4 = (const float4*)nf;
        float* bufs[2] = { (float*)s_buf, tile2 };
        const int nt = (e1 - s1 + 255) >> 8;

        float2 wv0 = w1frag[((warp +  0) << 5) | lane];
        float2 wv1 = w1frag[((warp +  8) << 5) | lane];
        float2 wv2 = w1frag[((warp + 16) << 5) | lane];
        float2 wv3 = w1frag[((warp + 24) << 5) | lane];
        float2 bp0 = b1frag[((warp +  0) << 2) | q4];
        float2 bp1 = b1frag[((warp +  8) << 2) | q4];
        float2 bp2 = b1frag[((warp + 16) << 2) | q4];
        float2 bp3 = b1frag[((warp + 24) << 2) | q4];

        u64 ss01[4] = {0ull,0ull,0ull,0ull};
        u64 qq01[4] = {0ull,0ull,0ull,0ull};

        gather_tile(s1, e1, bufs[0], t, eidx, nf4);
        __syncthreads();

        for (int it = 0; it < nt; it++) {
            if (it + 1 < nt)
                gather_tile(s1 + (it + 1) * 256, e1, bufs[(it + 1) & 1], t, eidx, nf4);

            const float2* tp = (const float2*)bufs[it & 1];   // float2-indexed tile
            // preload et=0 fragment (prefetch rotation hides LDS latency)
            float2 flo = tp[g * 4 + q4];
            float2 fhi = tp[(g + 8) * 4 + q4];
            #pragma unroll 4
            for (int et = 0; et < 32; et++) {
                int rn = ((et + 1) & 31) * 16 + g;
                float2 nlo = tp[rn * 4 + q4];
                float2 nhi = tp[(rn + 8) * 4 + q4];
                unsigned a0 = __float_as_uint(flo.x), a2 = __float_as_uint(flo.y);
                unsigned a1 = __float_as_uint(fhi.x), a3 = __float_as_uint(fhi.y);
                float h0, h1, h2, h3;
                u64 P01, P23;
                mma_init(h0, h1, h2, h3, a0, a1, a2, a3,
                         __float_as_uint(wv0.x), __float_as_uint(wv0.y),
                         bp0.x, bp0.y, bp0.x, bp0.y);
                P01 = pack2(fmaxf(h0, 0.f), fmaxf(h1, 0.f));
                P23 = pack2(fmaxf(h2, 0.f), fmaxf(h3, 0.f));
                ss01[0] = add2(ss01[0], P01); ss01[0] = add2(ss01[0], P23);
                qq01[0] = fma2(P01, P01, qq01[0]); qq01[0] = fma2(P23, P23, qq01[0]);
                mma_init(h0, h1, h2, h3, a0, a1, a2, a3,
                         __float_as_uint(wv1.x), __float_as_uint(wv1.y),
                         bp1.x, bp1.y, bp1.x, bp1.y);
                P01 = pack2(fmaxf(h0, 0.f), fmaxf(h1, 0.f));
                P23 = pack2(fmaxf(h2, 0.f), fmaxf(h3, 0.f));
                ss01[1] = add2(ss01[1], P01); ss01[1] = add2(ss01[1], P23);
                qq01[1] = fma2(P01, P01, qq01[1]); qq01[1] = fma2(P23, P23, qq01[1]);
                mma_init(h0, h1, h2, h3, a0, a1, a2, a3,
                         __float_as_uint(wv2.x), __float_as_uint(wv2.y),
                         bp2.x, bp2.y, bp2.x, bp2.y);
                P01 = pack2(fmaxf(h0, 0.f), fmaxf(h1, 0.f));
                P23 = pack2(fmaxf(h2, 0.f), fmaxf(h3, 0.f));
                ss01[2] = add2(ss01[2], P01); ss01[2] = add2(ss01[2], P23);
                qq01[2] = fma2(P01, P01, qq01[2]); qq01[2] = fma2(P23, P23, qq01[2]);
                mma_init(h0, h1, h2, h3, a0, a1, a2, a3,
                         __float_as_uint(wv3.x), __float_as_uint(wv3.y),
                         bp3.x, bp3.y, bp3.x, bp3.y);
                P01 = pack2(fmaxf(h0, 0.f), fmaxf(h1, 0.f));
                P23 = pack2(fmaxf(h2, 0.f), fmaxf(h3, 0.f));
                ss01[3] = add2(ss01[3], P01); ss01[3] = add2(ss01[3], P23);
                qq01[3] = fma2(P01, P01, qq01[3]); qq01[3] = fma2(P23, P23, qq01[3]);
                flo = nlo; fhi = nhi;
            }
            __syncthreads();
        }

        // unpack, reduce over g lanes (xor 4, 8, 16), commit
        #pragma unroll
        for (int i = 0; i < 4; i++) {
            float ss0, ss1, qv0, qv1;
            unpack2(ss01[i], ss0, ss1);
            unpack2(qq01[i], qv0, qv1);
            #pragma unroll
            for (int off = 4; off <= 16; off <<= 1) {
                ss0 += __shfl_xor_sync(0xffffffffu, ss0, off);
                ss1 += __shfl_xor_sync(0xffffffffu, ss1, off);
                qv0 += __shfl_xor_sync(0xffffffffu, qv0, off);
                qv1 += __shfl_xor_sync(0xffffffffu, qv1, off);
            }
            if (lane < 4) {
                int q = warp + 8 * i;
                int col = q * 8 + 2 * q4;
                atomicAdd(&g_sum[col],     ss0);
                atomicAdd(&g_sum[col + 1], ss1);
                atomicAdd(&g_sumsq[col],     qv0);
                atomicAdd(&g_sumsq[col + 1], qv1);
            }
        }
    }

    // ============ grid barrier ============
    __syncthreads();
    if (t == 0) {
        __threadfence();
        if (atomicAdd(&g_arrive, 1) == GRID - 1) {
            g_release = 1;
        } else {
            while (g_release == 0) { }
        }
        __threadfence();
    }
    __syncthreads();

    // ============ finalize BN (fake-row corrected), dh, mfrag ============
    {
        const float invE = 1.f / (float)E_NUM;
        float rb = fmaxf(b1[t], 0.f);
        float sum   = g_sum[t]   - (float)NFAKE * rb;
        float sumsq = g_sumsq[t] - (float)NFAKE * rb * rb;
        float mu  = sum * invE;
        float var = sumsq * invE - mu * mu;
        float aj  = gamma[t] * rsqrtf(var + BN_EPS);
        a_s[t] = aj;
        c_s[t] = beta[t] - mu * aj;
    }
    __syncthreads();
    {
        float acc = 0.f;
        for (int j = lane; j < H_DIM; j += 32) acc += c_s[j] * g_Craw[j * 8 + warp];
        acc = wred(acc);
        if (lane == 0) dhf[warp] = 0.5f * (acc + g_biaspart[warp]);
    }
    for (int i = t; i < 1024; i += 256) {
        int q = i >> 5, l = i & 31;
        int kk = l & 3, nn = l >> 2;
        // GEMM2 B rows tau-permuted: slot kk -> j = q*8+2kk; slot kk+4 -> j = q*8+2kk+1
        int j0 = q * 8 + 2 * kk;
        float m0 = 0.5f * a_s[j0] * g_Craw[j0 * 8 + nn];
        float m1 = 0.5f * a_s[j0 + 1] * g_Craw[(j0 + 1) * 8 + nn];
        mfrag[i] = make_float2(__uint_as_float(tf32r(m0)), __uint_as_float(tf32r(m1)));
    }
    __syncthreads();

    // ====== phase 2: tensor contraction, 2 tiles x even/odd split acc ======
    {
        const int warp_gid = b * 8 + warp;
        const float dh0 = dhf[2 * q4], dh1 = dhf[2 * q4 + 1];

        int tau = warp_gid;
        for (; tau + NWARPS < NTILES; tau += 2 * NWARPS) {
            int peX = tau << 4;
            int peY = (tau + NWARPS) << 4;
            const float2* rX = (const float2*)(g_ncf + (size_t)(peX + g) * 8);
            const float2* rY = (const float2*)(g_ncf + (size_t)(peY + g) * 8);
            float2 Xlo = rX[q4], Xhi = rX[32 + q4];
            float2 Ylo = rY[q4], Yhi = rY[32 + q4];
            unsigned aX0 = __float_as_uint(Xlo.x), aX2 = __float_as_uint(Xlo.y);
            unsigned aX1 = __float_as_uint(Xhi.x), aX3 = __float_as_uint(Xhi.y);
            unsigned aY0 = __float_as_uint(Ylo.x), aY2 = __float_as_uint(Ylo.y);
            unsigned aY1 = __float_as_uint(Yhi.x), aY3 = __float_as_uint(Yhi.y);
            // even/odd accumulator split halves the serial mma chain
            float cXe0 = dh0, cXe1 = dh1, cXe2 = dh0, cXe3 = dh1;
            float cXo0 = 0.f, cXo1 = 0.f, cXo2 = 0.f, cXo3 = 0.f;
            float cYe0 = dh0, cYe1 = dh1, cYe2 = dh0, cYe3 = dh1;
            float cYo0 = 0.f, cYo1 = 0.f, cYo2 = 0.f, cYo3 = 0.f;

            #pragma unroll 4
            for (int q = 0; q < 32; q += 2) {
                {   // even q
                    float2 bpv = b1frag[(q << 2) | q4];
                    float2 wv = w1frag[(q << 5) | lane];
                    float2 mv = mfrag[(q << 5) | lane];
                    unsigned wb0 = __float_as_uint(wv.x), wb1 = __float_as_uint(wv.y);
                    unsigned mb0 = __float_as_uint(mv.x), mb1 = __float_as_uint(mv.y);
                    float hX0, hX1, hX2, hX3, hY0, hY1, hY2, hY3;
                    mma_init(hX0, hX1, hX2, hX3, aX0, aX1, aX2, aX3, wb0, wb1,
                             bpv.x, bpv.y, bpv.x, bpv.y);
                    mma_init(hY0, hY1, hY2, hY3, aY0, aY1, aY2, aY3, wb0, wb1,
                             bpv.x, bpv.y, bpv.x, bpv.y);
                    unsigned xX0 = __float_as_uint(fmaxf(hX0, 0.f));
                    unsigned xX1 = __float_as_uint(fmaxf(hX2, 0.f));
                    unsigned xX2 = __float_as_uint(fmaxf(hX1, 0.f));
                    unsigned xX3 = __float_as_uint(fmaxf(hX3, 0.f));
                    unsigned xY0 = __float_as_uint(fmaxf(hY0, 0.f));
                    unsigned xY1 = __float_as_uint(fmaxf(hY2, 0.f));
                    unsigned xY2 = __float_as_uint(fmaxf(hY1, 0.f));
                    unsigned xY3 = __float_as_uint(fmaxf(hY3, 0.f));
                    mma_acc(cXe0, cXe1, cXe2, cXe3, xX0, xX1, xX2, xX3, mb0, mb1);
                    mma_acc(cYe0, cYe1, cYe2, cYe3, xY0, xY1, xY2, xY3, mb0, mb1);
                }
                {   // odd q+1
                    int qo = q + 1;
                    float2 bpv = b1frag[(qo << 2) | q4];
                    float2 wv = w1frag[(qo << 5) | lane];
                    float2 mv = mfrag[(qo << 5) | lane];
                    unsigned wb0 = __float_as_uint(wv.x), wb1 = __float_as_uint(wv.y);
                    unsigned mb0 = __float_as_uint(mv.x), mb1 = __float_as_uint(mv.y);
                    float hX0, hX1, hX2, hX3, hY0, hY1, hY2, hY3;
                    mma_init(hX0, hX1, hX2, hX3, aX0, aX1, aX2, aX3, wb0, wb1,
                             bpv.x, bpv.y, bpv.x, bpv.y);
                    mma_init(hY0, hY1, hY2, hY3, aY0, aY1, aY2, aY3, wb0, wb1,
                             bpv.x, bpv.y, bpv.x, bpv.y);
                    unsigned xX0 = __float_as_uint(fmaxf(hX0, 0.f));
                    unsigned xX1 = __float_as_uint(fmaxf(hX2, 0.f));
                    unsigned xX2 = __float_as_uint(fmaxf(hX1, 0.f));
                    unsigned xX3 = __float_as_uint(fmaxf(hX3, 0.f));
                    unsigned xY0 = __float_as_uint(fmaxf(hY0, 0.f));
                    unsigned xY1 = __float_as_uint(fmaxf(hY2, 0.f));
                    unsigned xY2 = __float_as_uint(fmaxf(hY1, 0.f));
                    unsigned xY3 = __float_as_uint(fmaxf(hY3, 0.f));
                    mma_acc(cXo0, cXo1, cXo2, cXo3, xX0, xX1, xX2, xX3, mb0, mb1);
                    mma_acc(cYo0, cYo1, cYo2, cYo3, xY0, xY1, xY2, xY3, mb0, mb1);
                }
            }

            float cX0 = cXe0 + cXo0, cX1 = cXe1 + cXo1;
            float cX2 = cXe2 + cXo2, cX3 = cXe3 + cXo3;
            float cY0 = cYe0 + cYo0, cY1 = cYe1 + cYo1;
            float cY2 = cYe2 + cYo2, cY3 = cYe3 + cYo3;

            size_t oX = (size_t)(peX + g) * 8 + 2 * q4;
            size_t oY = (size_t)(peY + g) * 8 + 2 * q4;
            float2 eX1 = *(const float2*)(ea + oX);
            float2 eX2 = *(const float2*)(ea + oX + 64);
            float2 eY1 = *(const float2*)(ea + oY);
            float2 eY2 = *(const float2*)(ea + oY + 64);
            *(float2*)(out + oX)      = make_float2(eX1.x + cX0, eX1.y + cX1);
            *(float2*)(out + oX + 64) = make_float2(eX2.x + cX2, eX2.y + cX3);
            *(float2*)(out + oY)      = make_float2(eY1.x + cY0, eY1.y + cY1);
            *(float2*)(out + oY + 64) = make_float2(eY2.x + cY2, eY2.y + cY3);
        }
        if (tau < NTILES) {
            int pe = tau << 4;
            const float2* r0p = (const float2*)(g_ncf + (size_t)(pe + g) * 8);
            float2 lo = r0p[q4], hi = r0p[32 + q4];
            unsigned a0 = __float_as_uint(lo.x), a2 = __float_as_uint(lo.y);
            unsigned a1 = __float_as_uint(hi.x), a3 = __float_as_uint(hi.y);
            float ce0 = dh0, ce1 = dh1, ce2 = dh0, ce3 = dh1;
            float co0 = 0.f, co1 = 0.f, co2 = 0.f, co3 = 0.f;
            #pragma unroll 4
            for (int q = 0; q < 32; q += 2) {
                {
                    float2 bpv = b1frag[(q << 2) | q4];
                    float2 wv = w1frag[(q << 5) | lane];
                    float2 mv = mfrag[(q << 5) | lane];
                    float h0, h1, h2, h3;
                    mma_init(h0, h1, h2, h3, a0, a1, a2, a3,
                             __float_as_uint(wv.x), __float_as_uint(wv.y),
                             bpv.x, bpv.y, bpv.x, bpv.y);
                    unsigned x0 = __float_as_uint(fmaxf(h0, 0.f));
                    unsigned x1 = __float_as_uint(fmaxf(h2, 0.f));
                    unsigned x2 = __float_as_uint(fmaxf(h1, 0.f));
                    unsigned x3 = __float_as_uint(fmaxf(h3, 0.f));
                    mma_acc(ce0, ce1, ce2, ce3, x0, x1, x2, x3,
                            __float_as_uint(mv.x), __float_as_uint(mv.y));
                }
                {
                    int qo = q + 1;
                    float2 bpv = b1frag[(qo << 2) | q4];
                    float2 wv = w1frag[(qo << 5) | lane];
                    float2 mv = mfrag[(qo << 5) | lane];
                    float h0, h1, h2, h3;
                    mma_init(h0, h1, h2, h3, a0, a1, a2, a3,
                             __float_as_uint(wv.x), __float_as_uint(wv.y),
                             bpv.x, bpv.y, bpv.x, bpv.y);
                    unsigned x0 = __float_as_uint(fmaxf(h0, 0.f));
                    unsigned x1 = __float_as_uint(fmaxf(h2, 0.f));
                    unsigned x2 = __float_as_uint(fmaxf(h1, 0.f));
                    unsigned x3 = __float_as_uint(fmaxf(h3, 0.f));
                    mma_acc(co0, co1, co2, co3, x0, x1, x2, x3,
                            __float_as_uint(mv.x), __float_as_uint(mv.y));
                }
            }
            float c0 = ce0 + co0, c1 = ce1 + co1, c2 = ce2 + co2, c3 = ce3 + co3;
            size_t o1 = (size_t)(pe + g) * 8 + 2 * q4;
            float2 e1 = *(const float2*)(ea + o1);
            float2 e2v = *(const float2*)(ea + o1 + 64);
            *(float2*)(out + o1)      = make_float2(e1.x + c0, e1.y + c1);
            *(float2*)(out + o1 + 64) = make_float2(e2v.x + c2, e2v.y + c3);
        }
    }

    // ============ reset (last finisher) ============
    __syncthreads();
    if (t == 0) {
        __threadfence();
        if (atomicAdd(&g_finish, 1) == GRID - 1) {
            g_arrive = 0;
            g_release = 0;
            for (int i = 0; i < H_DIM; i++) { g_sum[i] = 0.f; g_sumsq[i] = 0.f; }
            __threadfence();
            g_finish = 0;
        }
    }
}

// -------- launch --------
extern "C" void kernel_launch(void* const* d_in, const int* in_sizes, int n_in,
                              void* d_out, int out_size) {
    (void)in_sizes; (void)n_in; (void)out_size;
    const float* edge_attr = (const float*)d_in[0];
    const float* nf        = (const float*)d_in[1];
    const int*   eidx      = (const int*)d_in[2];
    // d_in[3..8] = edge-encoder weights: dead code in the reference
    const float* W1    = (const float*)d_in[9];
    const float* b1    = (const float*)d_in[10];
    const float* gamma = (const float*)d_in[11];
    const float* beta  = (const float*)d_in[12];
    const float* W2    = (const float*)d_in[13];
    const float* b2    = (const float*)d_in[14];
    const float* Wv    = (const float*)d_in[15];
    const float* bv    = (const float*)d_in[16];
    const float* Wo    = (const float*)d_in[17];
    const float* bo    = (const float*)d_in[18];
    const float* Wp    = (const float*)d_in[19];
    const float* bp    = (const float*)d_in[20];
    float* out = (float*)d_out;

    fused<<<GRID, 256>>>(edge_attr, nf, eidx, W1, b1, gamma, beta,
                         W2, b2, Wv, bv, Wo, bo, Wp, bp, out);
}

// round 16
// speedup vs baseline: 1.5615x; 1.5615x over previous
#include <cuda_runtime.h>
#include <cstdint>

#define E_NUM   500000
#define H_DIM   256
#define PAIRS   (E_NUM / 2)      // 250000
#define BN_EPS  1e-5f
#define GRID    296              // 148 SMs x 2 co-resident blocks (3/SM toxic: R4/R10)
#define PER1    848              // pairs/block for stats, blocks 1..295
#define NTILES  31250            // E/16 edge tiles for tensor phase 2
#define NWARPS  (GRID * 8)       // 2368 warps
#define NFAKE   103648           // zero-padded fake edges in stats (exact for PER1=848)

typedef unsigned long long u64;

// -------- device scratch (static, no allocation) --------
__device__ float g_sum[H_DIM];                     // zero-init
__device__ float g_sumsq[H_DIM];
__device__ __align__(16) float g_ncf[(size_t)E_NUM * 8];  // raw (src+tgt) [E,8], 16MB
__device__ float g_Craw[H_DIM * 8];                // W2@Wv@Wo@Wp
__device__ float g_biaspart[8];                    // b2@P2 + bv@P1 + bo@Wp + bp
__device__ unsigned g_arrive = 0;
__device__ volatile unsigned g_release = 0;
__device__ unsigned g_finish = 0;

// -------- helpers --------
__device__ __forceinline__ float wred(float v) {
    v += __shfl_down_sync(0xffffffffu, v, 16);
    v += __shfl_down_sync(0xffffffffu, v, 8);
    v += __shfl_down_sync(0xffffffffu, v, 4);
    v += __shfl_down_sync(0xffffffffu, v, 2);
    v += __shfl_down_sync(0xffffffffu, v, 1);
    return v;
}
__device__ __forceinline__ unsigned tf32r(float x) {
    unsigned u;
    asm("cvt.rna.tf32.f32 %0, %1;" : "=r"(u) : "f"(x));
    return u;
}
__device__ __forceinline__ u64 pack2(float lo, float hi) {
    u64 r;
    asm("mov.b64 %0, {%1, %2};" : "=l"(r)
        : "r"(__float_as_uint(lo)), "r"(__float_as_uint(hi)));
    return r;
}
__device__ __forceinline__ void unpack2(u64 v, float &lo, float &hi) {
    unsigned int a, b;
    asm("mov.b64 {%0, %1}, %2;" : "=r"(a), "=r"(b) : "l"(v));
    lo = __uint_as_float(a); hi = __uint_as_float(b);
}
__device__ __forceinline__ u64 fma2(u64 a, u64 b, u64 c) {
    u64 d;
    asm("fma.rn.f32x2 %0, %1, %2, %3;" : "=l"(d) : "l"(a), "l"(b), "l"(c));
    return d;
}
__device__ __forceinline__ u64 add2(u64 a, u64 b) {
    u64 d;
    asm("add.rn.f32x2 %0, %1, %2;" : "=l"(d) : "l"(a), "l"(b));
    return d;
}
__device__ __forceinline__ void mma_init(float &d0, float &d1, float &d2, float &d3,
    unsigned a0, unsigned a1, unsigned a2, unsigned a3,
    unsigned b0, unsigned b1,
    float c0, float c1, float c2, float c3) {
    asm("mma.sync.aligned.m16n8k8.row.col.f32.tf32.tf32.f32 "
        "{%0,%1,%2,%3}, {%4,%5,%6,%7}, {%8,%9}, {%10,%11,%12,%13};"
        : "=f"(d0), "=f"(d1), "=f"(d2), "=f"(d3)
        : "r"(a0), "r"(a1), "r"(a2), "r"(a3), "r"(b0), "r"(b1),
          "f"(c0), "f"(c1), "f"(c2), "f"(c3));
}
__device__ __forceinline__ void mma_acc(float &c0, float &c1, float &c2, float &c3,
    unsigned a0, unsigned a1, unsigned a2, unsigned a3,
    unsigned b0, unsigned b1) {
    asm("mma.sync.aligned.m16n8k8.row.col.f32.tf32.tf32.f32 "
        "{%0,%1,%2,%3}, {%4,%5,%6,%7}, {%8,%9}, {%0,%1,%2,%3};"
        : "+f"(c0), "+f"(c1), "+f"(c2), "+f"(c3)
        : "r"(a0), "r"(a1), "r"(a2), "r"(a3), "r"(b0), "r"(b1));
}

// gather one 256-pair tile: raw (src+tgt), no cvt, no 0.5 (folded into W1)
__device__ __forceinline__ void gather_tile(
    int base, int e1, float* buf, int t,
    const int* __restrict__ eidx, const float4* __restrict__ nf4)
{
    float4* row0 = (float4*)(buf + (2 * t) * 8);
    int p = base + t;
    if (p < e1) {
        int e0 = 2 * p;
        int sA = eidx[e0],         sB = eidx[e0 + 1];
        int dA = eidx[E_NUM + e0], dB = eidx[E_NUM + e0 + 1];
        float4 sa0 = nf4[2*sA], sa1 = nf4[2*sA+1];
        float4 da0 = nf4[2*dA], da1 = nf4[2*dA+1];
        float4 sb0 = nf4[2*sB], sb1 = nf4[2*sB+1];
        float4 db0 = nf4[2*dB], db1 = nf4[2*dB+1];
        float4 vl0 = make_float4(sa0.x+da0.x, sa0.y+da0.y, sa0.z+da0.z, sa0.w+da0.w);
        float4 vl1 = make_float4(sa1.x+da1.x, sa1.y+da1.y, sa1.z+da1.z, sa1.w+da1.w);
        float4 vh0 = make_float4(sb0.x+db0.x, sb0.y+db0.y, sb0.z+db0.z, sb0.w+db0.w);
        float4 vh1 = make_float4(sb1.x+db1.x, sb1.y+db1.y, sb1.z+db1.z, sb1.w+db1.w);
        row0[0] = vl0; row0[1] = vl1; row0[2] = vh0; row0[3] = vh1;
        float4* nr = (float4*)(g_ncf + (size_t)(2 * p) * 8);
        nr[0] = vl0; nr[1] = vl1; nr[2] = vh0; nr[3] = vh1;
    } else {
        float4 z = make_float4(0.f, 0.f, 0.f, 0.f);
        row0[0] = z; row0[1] = z; row0[2] = z; row0[3] = z;
    }
}

__global__ void __launch_bounds__(256, 2)
fused(const float* __restrict__ ea, const float* __restrict__ nf,
      const int*   __restrict__ eidx,
      const float* __restrict__ W1, const float* __restrict__ b1,
      const float* __restrict__ gamma, const float* __restrict__ beta,
      const float* __restrict__ W2, const float* __restrict__ b2,
      const float* __restrict__ Wv, const float* __restrict__ bv,
      const float* __restrict__ Wo, const float* __restrict__ bo,
      const float* __restrict__ Wp, const float* __restrict__ bp,
      float* __restrict__ out)
{
    // s_buf: phase1 buf0 (16KB of it) / block0 chain (2x2304 floats = 18KB)
    __shared__ __align__(16) unsigned char s_buf[18432];
    __shared__ __align__(16) float tile2[4096];     // phase1 buf1 (16KB)
    __shared__ __align__(16) float2 w1frag[1024];   // GEMM1 B frags = tf32(0.5*W1)
    __shared__ __align__(16) float2 mfrag[1024];    // GEMM2 B frags (tau-permuted)
    __shared__ float2 b1frag[128];                  // b1 col pairs
    __shared__ float dhf[8];
    __shared__ float a_s[H_DIM], c_s[H_DIM];

    const int t = threadIdx.x;
    const int b = blockIdx.x;
    const int lane = t & 31, warp = t >> 5;
    const int g = lane >> 2, q4 = lane & 3;

    // ---- W1 (0.5-folded) / b1 fragment tables ----
    for (int i = t; i < 1024; i += 256) {
        int q = i >> 5, l = i & 31;
        int kk = l & 3, nn = l >> 2;
        float w0 = 0.5f * W1[kk * H_DIM + q * 8 + nn];
        float w1v = 0.5f * W1[(kk + 4) * H_DIM + q * 8 + nn];
        w1frag[i] = make_float2(__uint_as_float(tf32r(w0)), __uint_as_float(tf32r(w1v)));
    }
    for (int i = t; i < 128; i += 256) {
        int q = i >> 2, qq = i & 3;
        b1frag[i] = make_float2(b1[q * 8 + 2 * qq], b1[q * 8 + 2 * qq + 1]);
    }
    __syncthreads();

    if (b == 0) {
        // ============ weight chain (overlaps the stats pass) ============
        float* bufA = (float*)s_buf;
        float* bufB = bufA + 2304;
        for (int i = t; i < H_DIM * 8; i += 256)
            bufA[(i >> 3) * 9 + (i & 7)] = Wp[i];
        __syncthreads();
        float biask = 0.f;
        for (int j = lane; j < H_DIM; j += 32) biask += bo[j] * bufA[j * 9 + warp];
        for (int jj = warp; jj < H_DIM; jj += 8) {
            float a0=0,a1=0,a2=0,a3=0,a4=0,a5=0,a6=0,a7=0;
            #pragma unroll
            for (int qb = 0; qb < 8; qb++) {
                int q = qb * 32 + lane;
                float av = Wo[jj * H_DIM + q];
                const float* ir = bufA + q * 9;
                a0 += av*ir[0]; a1 += av*ir[1]; a2 += av*ir[2]; a3 += av*ir[3];
                a4 += av*ir[4]; a5 += av*ir[5]; a6 += av*ir[6]; a7 += av*ir[7];
            }
            a0=wred(a0); a1=wred(a1); a2=wred(a2); a3=wred(a3);
            a4=wred(a4); a5=wred(a5); a6=wred(a6); a7=wred(a7);
            if (lane == 0) {
                float* orow = bufB + jj * 9;
                orow[0]=a0; orow[1]=a1; orow[2]=a2; orow[3]=a3;
                orow[4]=a4; orow[5]=a5; orow[6]=a6; orow[7]=a7;
            }
        }
        __syncthreads();
        for (int j = lane; j < H_DIM; j += 32) biask += bv[j] * bufB[j * 9 + warp];
        for (int jj = warp; jj < H_DIM; jj += 8) {
            float a0=0,a1=0,a2=0,a3=0,a4=0,a5=0,a6=0,a7=0;
            #pragma unroll
            for (int qb = 0; qb < 8; qb++) {
                int q = qb * 32 + lane;
                float av = Wv[jj * H_DIM + q];
                const float* ir = bufB + q * 9;
                a0 += av*ir[0]; a1 += av*ir[1]; a2 += av*ir[2]; a3 += av*ir[3];
                a4 += av*ir[4]; a5 += av*ir[5]; a6 += av*ir[6]; a7 += av*ir[7];
            }
            a0=wred(a0); a1=wred(a1); a2=wred(a2); a3=wred(a3);
            a4=wred(a4); a5=wred(a5); a6=wred(a6); a7=wred(a7);
            if (lane == 0) {
                float* orow = bufA + jj * 9;
                orow[0]=a0; orow[1]=a1; orow[2]=a2; orow[3]=a3;
                orow[4]=a4; orow[5]=a5; orow[6]=a6; orow[7]=a7;
            }
        }
        __syncthreads();
        for (int j = lane; j < H_DIM; j += 32) biask += b2[j] * bufA[j * 9 + warp];
        for (int jj = warp; jj < H_DIM; jj += 8) {
            float a0=0,a1=0,a2=0,a3=0,a4=0,a5=0,a6=0,a7=0;
            #pragma unroll
            for (int qb = 0; qb < 8; qb++) {
                int q = qb * 32 + lane;
                float av = W2[jj * H_DIM + q];
                const float* ir = bufA + q * 9;
                a0 += av*ir[0]; a1 += av*ir[1]; a2 += av*ir[2]; a3 += av*ir[3];
                a4 += av*ir[4]; a5 += av*ir[5]; a6 += av*ir[6]; a7 += av*ir[7];
            }
            a0=wred(a0); a1=wred(a1); a2=wred(a2); a3=wred(a3);
            a4=wred(a4); a5=wred(a5); a6=wred(a6); a7=wred(a7);
            if (lane == 0) {
                float* orow = g_Craw + jj * 8;
                orow[0]=a0; orow[1]=a1; orow[2]=a2; orow[3]=a3;
                orow[4]=a4; orow[5]=a5; orow[6]=a6; orow[7]=a7;
            }
        }
        biask = wred(biask);
        if (lane == 0) g_biaspart[warp] = biask + bp[warp];
    } else {
        // ===== phase 1: double-buffered gather + tensor relu stats (R13 verbatim) =====
        int s1 = (b - 1) * PER1;
        int e1 = s1 + PER1; if (e1 > PAIRS) e1 = PAIRS;
        const float4* nf4 = (const float4*)nf;
        float* bufs[2] = { (float*)s_buf, tile2 };
        const int nt = (e1 - s1 + 255) >> 8;

        float2 wv0 = w1frag[((warp +  0) << 5) | lane];
        float2 wv1 = w1frag[((warp +  8) << 5) | lane];
        float2 wv2 = w1frag[((warp + 16) << 5) | lane];
        float2 wv3 = w1frag[((warp + 24) << 5) | lane];
        float2 bp0 = b1frag[((warp +  0) << 2) | q4];
        float2 bp1 = b1frag[((warp +  8) << 2) | q4];
        float2 bp2 = b1frag[((warp + 16) << 2) | q4];
        float2 bp3 = b1frag[((warp + 24) << 2) | q4];

        u64 ss01[4] = {0ull,0ull,0ull,0ull};
        u64 qq01[4] = {0ull,0ull,0ull,0ull};

        gather_tile(s1, e1, bufs[0], t, eidx, nf4);
        __syncthreads();

        for (int it = 0; it < nt; it++) {
            if (it + 1 < nt)
                gather_tile(s1 + (it + 1) * 256, e1, bufs[(it + 1) & 1], t, eidx, nf4);

            const float* tile = bufs[it & 1];
            #pragma unroll 4
            for (int et = 0; et < 32; et++) {
                int r0 = et * 16 + g;
                unsigned a0 = __float_as_uint(tile[r0 * 8 + q4]);
                unsigned a1 = __float_as_uint(tile[(r0 + 8) * 8 + q4]);
                unsigned a2 = __float_as_uint(tile[r0 * 8 + q4 + 4]);
                unsigned a3 = __float_as_uint(tile[(r0 + 8) * 8 + q4 + 4]);
                float h0, h1, h2, h3;
                u64 P01, P23;
                mma_init(h0, h1, h2, h3, a0, a1, a2, a3,
                         __float_as_uint(wv0.x), __float_as_uint(wv0.y),
                         bp0.x, bp0.y, bp0.x, bp0.y);
                P01 = pack2(fmaxf(h0, 0.f), fmaxf(h1, 0.f));
                P23 = pack2(fmaxf(h2, 0.f), fmaxf(h3, 0.f));
                ss01[0] = add2(ss01[0], P01); ss01[0] = add2(ss01[0], P23);
                qq01[0] = fma2(P01, P01, qq01[0]); qq01[0] = fma2(P23, P23, qq01[0]);
                mma_init(h0, h1, h2, h3, a0, a1, a2, a3,
                         __float_as_uint(wv1.x), __float_as_uint(wv1.y),
                         bp1.x, bp1.y, bp1.x, bp1.y);
                P01 = pack2(fmaxf(h0, 0.f), fmaxf(h1, 0.f));
                P23 = pack2(fmaxf(h2, 0.f), fmaxf(h3, 0.f));
                ss01[1] = add2(ss01[1], P01); ss01[1] = add2(ss01[1], P23);
                qq01[1] = fma2(P01, P01, qq01[1]); qq01[1] = fma2(P23, P23, qq01[1]);
                mma_init(h0, h1, h2, h3, a0, a1, a2, a3,
                         __float_as_uint(wv2.x), __float_as_uint(wv2.y),
                         bp2.x, bp2.y, bp2.x, bp2.y);
                P01 = pack2(fmaxf(h0, 0.f), fmaxf(h1, 0.f));
                P23 = pack2(fmaxf(h2, 0.f), fmaxf(h3, 0.f));
                ss01[2] = add2(ss01[2], P01); ss01[2] = add2(ss01[2], P23);
                qq01[2] = fma2(P01, P01, qq01[2]); qq01[2] = fma2(P23, P23, qq01[2]);
                mma_init(h0, h1, h2, h3, a0, a1, a2, a3,
                         __float_as_uint(wv3.x), __float_as_uint(wv3.y),
                         bp3.x, bp3.y, bp3.x, bp3.y);
                P01 = pack2(fmaxf(h0, 0.f), fmaxf(h1, 0.f));
                P23 = pack2(fmaxf(h2, 0.f), fmaxf(h3, 0.f));
                ss01[3] = add2(ss01[3], P01); ss01[3] = add2(ss01[3], P23);
                qq01[3] = fma2(P01, P01, qq01[3]); qq01[3] = fma2(P23, P23, qq01[3]);
            }
            __syncthreads();
        }

        // unpack, reduce over g lanes (xor 4, 8, 16), commit
        #pragma unroll
        for (int i = 0; i < 4; i++) {
            float ss0, ss1, qv0, qv1;
            unpack2(ss01[i], ss0, ss1);
            unpack2(qq01[i], qv0, qv1);
            #pragma unroll
            for (int off = 4; off <= 16; off <<= 1) {
                ss0 += __shfl_xor_sync(0xffffffffu, ss0, off);
                ss1 += __shfl_xor_sync(0xffffffffu, ss1, off);
                qv0 += __shfl_xor_sync(0xffffffffu, qv0, off);
                qv1 += __shfl_xor_sync(0xffffffffu, qv1, off);
            }
            if (lane < 4) {
                int q = warp + 8 * i;
                int col = q * 8 + 2 * q4;
                atomicAdd(&g_sum[col],     ss0);
                atomicAdd(&g_sum[col + 1], ss1);
                atomicAdd(&g_sumsq[col],     qv0);
                atomicAdd(&g_sumsq[col + 1], qv1);
            }
        }
    }

    // ============ grid barrier ============
    __syncthreads();
    if (t == 0) {
        __threadfence();
        if (atomicAdd(&g_arrive, 1) == GRID - 1) {
            g_release = 1;
        } else {
            while (g_release == 0) { }
        }
        __threadfence();
    }
    __syncthreads();

    // ============ finalize BN (fake-row corrected), dh, mfrag ============
    {
        const float invE = 1.f / (float)E_NUM;
        float rb = fmaxf(b1[t], 0.f);
        float sum   = g_sum[t]   - (float)NFAKE * rb;
        float sumsq = g_sumsq[t] - (float)NFAKE * rb * rb;
        float mu  = sum * invE;
        float var = sumsq * invE - mu * mu;
        float aj  = gamma[t] * rsqrtf(var + BN_EPS);
        a_s[t] = aj;
        c_s[t] = beta[t] - mu * aj;
    }
    __syncthreads();
    {
        float acc = 0.f;
        for (int j = lane; j < H_DIM; j += 32) acc += c_s[j] * g_Craw[j * 8 + warp];
        acc = wred(acc);
        if (lane == 0) dhf[warp] = 0.5f * (acc + g_biaspart[warp]);
    }
    for (int i = t; i < 1024; i += 256) {
        int q = i >> 5, l = i & 31;
        int kk = l & 3, nn = l >> 2;
        // GEMM2 B rows tau-permuted: slot kk -> j = q*8+2kk; slot kk+4 -> j = q*8+2kk+1
        int j0 = q * 8 + 2 * kk;
        float m0 = 0.5f * a_s[j0] * g_Craw[j0 * 8 + nn];
        float m1 = 0.5f * a_s[j0 + 1] * g_Craw[(j0 + 1) * 8 + nn];
        mfrag[i] = make_float2(__uint_as_float(tf32r(m0)), __uint_as_float(tf32r(m1)));
    }
    __syncthreads();

    // ====== phase 2: 2 tiles/warp, even/odd accumulator split (ONLY change vs R13) ======
    {
        const int warp_gid = b * 8 + warp;
        const float dh0 = dhf[2 * q4], dh1 = dhf[2 * q4 + 1];

        int tau = warp_gid;
        for (; tau + NWARPS < NTILES; tau += 2 * NWARPS) {
            int peX = tau << 4;
            int peY = (tau + NWARPS) << 4;
            const float* rX0 = g_ncf + (size_t)(peX + g) * 8;
            const float* rY0 = g_ncf + (size_t)(peY + g) * 8;
            unsigned aX0 = __float_as_uint(rX0[q4]);
            unsigned aX1 = __float_as_uint(rX0[64 + q4]);
            unsigned aX2 = __float_as_uint(rX0[q4 + 4]);
            unsigned aX3 = __float_as_uint(rX0[64 + q4 + 4]);
            unsigned aY0 = __float_as_uint(rY0[q4]);
            unsigned aY1 = __float_as_uint(rY0[64 + q4]);
            unsigned aY2 = __float_as_uint(rY0[q4 + 4]);
            unsigned aY3 = __float_as_uint(rY0[64 + q4 + 4]);
            float cX0 = dh0, cX1 = dh1, cX2 = dh0, cX3 = dh1;   // even-q chain
            float dX0 = 0.f, dX1 = 0.f, dX2 = 0.f, dX3 = 0.f;   // odd-q chain
            float cY0 = dh0, cY1 = dh1, cY2 = dh0, cY3 = dh1;
            float dY0 = 0.f, dY1 = 0.f, dY2 = 0.f, dY3 = 0.f;

            #pragma unroll 4
            for (int q = 0; q < 32; q++) {
                float2 bpv = b1frag[(q << 2) | q4];
                float2 wv = w1frag[(q << 5) | lane];
                float2 mv = mfrag[(q << 5) | lane];
                unsigned wb0 = __float_as_uint(wv.x), wb1 = __float_as_uint(wv.y);
                unsigned mb0 = __float_as_uint(mv.x), mb1 = __float_as_uint(mv.y);
                float hX0, hX1, hX2, hX3, hY0, hY1, hY2, hY3;
                mma_init(hX0, hX1, hX2, hX3, aX0, aX1, aX2, aX3, wb0, wb1,
                         bpv.x, bpv.y, bpv.x, bpv.y);
                mma_init(hY0, hY1, hY2, hY3, aY0, aY1, aY2, aY3, wb0, wb1,
                         bpv.x, bpv.y, bpv.x, bpv.y);
                unsigned xX0 = __float_as_uint(fmaxf(hX0, 0.f));
                unsigned xX1 = __float_as_uint(fmaxf(hX2, 0.f));
                unsigned xX2 = __float_as_uint(fmaxf(hX1, 0.f));
                unsigned xX3 = __float_as_uint(fmaxf(hX3, 0.f));
                unsigned xY0 = __float_as_uint(fmaxf(hY0, 0.f));
                unsigned xY1 = __float_as_uint(fmaxf(hY2, 0.f));
                unsigned xY2 = __float_as_uint(fmaxf(hY1, 0.f));
                unsigned xY3 = __float_as_uint(fmaxf(hY3, 0.f));
                if (q & 1) {
                    mma_acc(dX0, dX1, dX2, dX3, xX0, xX1, xX2, xX3, mb0, mb1);
                    mma_acc(dY0, dY1, dY2, dY3, xY0, xY1, xY2, xY3, mb0, mb1);
                } else {
                    mma_acc(cX0, cX1, cX2, cX3, xX0, xX1, xX2, xX3, mb0, mb1);
                    mma_acc(cY0, cY1, cY2, cY3, xY0, xY1, xY2, xY3, mb0, mb1);
                }
            }
            cX0 += dX0; cX1 += dX1; cX2 += dX2; cX3 += dX3;
            cY0 += dY0; cY1 += dY1; cY2 += dY2; cY3 += dY3;

            size_t oX = (size_t)(peX + g) * 8 + 2 * q4;
            size_t oY = (size_t)(peY + g) * 8 + 2 * q4;
            float2 eX1 = *(const float2*)(ea + oX);
            float2 eX2 = *(const float2*)(ea + oX + 64);
            float2 eY1 = *(const float2*)(ea + oY);
            float2 eY2 = *(const float2*)(ea + oY + 64);
            *(float2*)(out + oX)      = make_float2(eX1.x + cX0, eX1.y + cX1);
            *(float2*)(out + oX + 64) = make_float2(eX2.x + cX2, eX2.y + cX3);
            *(float2*)(out + oY)      = make_float2(eY1.x + cY0, eY1.y + cY1);
            *(float2*)(out + oY + 64) = make_float2(eY2.x + cY2, eY2.y + cY3);
        }
        if (tau < NTILES) {
            int pe = tau << 4;
            const float* r0 = g_ncf + (size_t)(pe + g) * 8;
            unsigned a0 = __float_as_uint(r0[q4]);
            unsigned a1 = __float_as_uint(r0[64 + q4]);
            unsigned a2 = __float_as_uint(r0[q4 + 4]);
            unsigned a3 = __float_as_uint(r0[64 + q4 + 4]);
            float c0 = dh0, c1 = dh1, c2 = dh0, c3 = dh1;
            float d0 = 0.f, d1 = 0.f, d2 = 0.f, d3 = 0.f;
            #pragma unroll 4
            for (int q = 0; q < 32; q++) {
                float2 bpv = b1frag[(q << 2) | q4];
                float2 wv = w1frag[(q << 5) | lane];
                float2 mv = mfrag[(q << 5) | lane];
                float h0, h1, h2, h3;
                mma_init(h0, h1, h2, h3, a0, a1, a2, a3,
                         __float_as_uint(wv.x), __float_as_uint(wv.y),
                         bpv.x, bpv.y, bpv.x, bpv.y);
                unsigned x0 = __float_as_uint(fmaxf(h0, 0.f));
                unsigned x1 = __float_as_uint(fmaxf(h2, 0.f));
                unsigned x2 = __float_as_uint(fmaxf(h1, 0.f));
                unsigned x3 = __float_as_uint(fmaxf(h3, 0.f));
                if (q & 1)
                    mma_acc(d0, d1, d2, d3, x0, x1, x2, x3,
                            __float_as_uint(mv.x), __float_as_uint(mv.y));
                else
                    mma_acc(c0, c1, c2, c3, x0, x1, x2, x3,
                            __float_as_uint(mv.x), __float_as_uint(mv.y));
            }
            c0 += d0; c1 += d1; c2 += d2; c3 += d3;
            size_t o1 = (size_t)(pe + g) * 8 + 2 * q4;
            float2 e1 = *(const float2*)(ea + o1);
            float2 e2v = *(const float2*)(ea + o1 + 64);
            *(float2*)(out + o1)      = make_float2(e1.x + c0, e1.y + c1);
            *(float2*)(out + o1 + 64) = make_float2(e2v.x + c2, e2v.y + c3);
        }
    }

    // ============ reset (last finisher) ============
    __syncthreads();
    if (t == 0) {
        __threadfence();
        if (atomicAdd(&g_finish, 1) == GRID - 1) {
            g_arrive = 0;
            g_release = 0;
            for (int i = 0; i < H_DIM; i++) { g_sum[i] = 0.f; g_sumsq[i] = 0.f; }
            __threadfence();
            g_finish = 0;
        }
    }
}

// -------- launch --------
extern "C" void kernel_launch(void* const* d_in, const int* in_sizes, int n_in,
                              void* d_out, int out_size) {
    (void)in_sizes; (void)n_in; (void)out_size;
    const float* edge_attr = (const float*)d_in[0];
    const float* nf        = (const float*)d_in[1];
    const int*   eidx      = (const int*)d_in[2];
    // d_in[3..8] = edge-encoder weights: dead code in the reference
    const float* W1    = (const float*)d_in[9];
    const float* b1    = (const float*)d_in[10];
    const float* gamma = (const float*)d_in[11];
    const float* beta  = (const float*)d_in[12];
    const float* W2    = (const float*)d_in[13];
    const float* b2    = (const float*)d_in[14];
    const float* Wv    = (const float*)d_in[15];
    const float* bv    = (const float*)d_in[16];
    const float* Wo    = (const float*)d_in[17];
    const float* bo    = (const float*)d_in[18];
    const float* Wp    = (const float*)d_in[19];
    const float* bp    = (const float*)d_in[20];
    float* out = (float*)d_out;

    fused<<<GRID, 256>>>(edge_attr, nf, eidx, W1, b1, gamma, beta,
                         W2, b2, Wv, bv, Wo, bo, Wp, bp, out);
}